// round 3
// baseline (speedup 1.0000x reference)
#include <cuda_runtime.h>

#define S_   38
#define R_   340
#define HC_  128
#define SC_  4
#define RC_  3
#define NO_  7
#define L_   4
#define BMAX 512
#define NMAX (BMAX * (S_ + R_))   // 193536
#define EMAX 3072000

// ---------------- scratch (device globals; no allocation allowed) ----------------
__device__ float d_X[NMAX * HC_];     // node features (99 MB)
__device__ float d_XW[NMAX * HC_];    // X @ W per layer (99 MB)
__device__ int   d_degi[NMAX];        // edge in-count (w/o self loop)
__device__ float d_dinv[NMAX];        // rsqrt(deg+1)
__device__ int   d_offs[NMAX];        // CSR row offsets (exclusive scan)
__device__ int   d_curs[NMAX];        // scatter cursors
__device__ int   d_bsum[512];         // scan block sums
__device__ int   d_esrc[EMAX];        // CSR: src node per sorted edge
__device__ float d_enorm[EMAX];       // CSR: dinv[s]*dinv[d] per sorted edge
__device__ float d_stats[16];         // bn sums: s sum[4],sq[4]; r sum[3],sq[3]
__device__ float d_pre[16];           // bn scale/shift: s sc[4],sh[4]; r sc[3],sh[3]
__device__ float d_O[BMAX * NO_];
__device__ float d_pooled[NMAX];

__device__ __forceinline__ float leaky(float x) { return x > 0.f ? x : 0.2f * x; }

// ---------------- init / degree / CSR ----------------
__global__ void k_zero(int n) {
    int i = blockIdx.x * blockDim.x + threadIdx.x;
    if (i < n) d_degi[i] = 0;
    if (i < 16) d_stats[i] = 0.f;
}

__global__ void k_count(const int* __restrict__ dst, int E) {
    int e = blockIdx.x * blockDim.x + threadIdx.x;
    if (e < E) atomicAdd(&d_degi[dst[e]], 1);
}

__global__ void k_dinv(int n) {
    int i = blockIdx.x * blockDim.x + threadIdx.x;
    if (i < n) d_dinv[i] = rsqrtf((float)(d_degi[i] + 1));
}

__global__ void k_scan1(int n) {
    __shared__ int sh[512];
    int t = threadIdx.x;
    int g = blockIdx.x * 512 + t;
    int v = (g < n) ? d_degi[g] : 0;
    sh[t] = v;
    __syncthreads();
    #pragma unroll
    for (int off = 1; off < 512; off <<= 1) {
        int a = sh[t];
        int b = (t >= off) ? sh[t - off] : 0;
        __syncthreads();
        sh[t] = a + b;
        __syncthreads();
    }
    if (g < n) d_offs[g] = sh[t] - v;           // exclusive within block
    if (t == 511) d_bsum[blockIdx.x] = sh[511]; // block total
}

__global__ void k_scan2(int nb) {
    __shared__ int sh[512];
    int t = threadIdx.x;
    int v = (t < nb) ? d_bsum[t] : 0;
    sh[t] = v;
    __syncthreads();
    #pragma unroll
    for (int off = 1; off < 512; off <<= 1) {
        int a = sh[t];
        int b = (t >= off) ? sh[t - off] : 0;
        __syncthreads();
        sh[t] = a + b;
        __syncthreads();
    }
    if (t < nb) d_bsum[t] = sh[t] - v;          // exclusive block offsets
}

__global__ void k_scan3(int n) {
    int g = blockIdx.x * blockDim.x + threadIdx.x;
    if (g < n) {
        int o = d_offs[g] + d_bsum[g >> 9];
        d_offs[g] = o;
        d_curs[g] = o;
    }
}

__global__ void k_fill(const int* __restrict__ src, const int* __restrict__ dst, int E) {
    int e = blockIdx.x * blockDim.x + threadIdx.x;
    if (e < E) {
        int s = src[e], d = dst[e];
        int p = atomicAdd(&d_curs[d], 1);
        d_esrc[p] = s;
        d_enorm[p] = d_dinv[s] * d_dinv[d];
    }
}

// ---------------- batchnorm stats ----------------
__global__ void k_stats_s(const float* __restrict__ sx, int rows) {
    const float4* v4 = (const float4*)sx;
    float s0 = 0, s1 = 0, s2 = 0, s3 = 0, q0 = 0, q1 = 0, q2 = 0, q3 = 0;
    for (int r = blockIdx.x * blockDim.x + threadIdx.x; r < rows; r += gridDim.x * blockDim.x) {
        float4 v = v4[r];
        s0 += v.x; q0 += v.x * v.x;
        s1 += v.y; q1 += v.y * v.y;
        s2 += v.z; q2 += v.z * v.z;
        s3 += v.w; q3 += v.w * v.w;
    }
    #pragma unroll
    for (int off = 16; off > 0; off >>= 1) {
        s0 += __shfl_down_sync(0xffffffffu, s0, off);
        s1 += __shfl_down_sync(0xffffffffu, s1, off);
        s2 += __shfl_down_sync(0xffffffffu, s2, off);
        s3 += __shfl_down_sync(0xffffffffu, s3, off);
        q0 += __shfl_down_sync(0xffffffffu, q0, off);
        q1 += __shfl_down_sync(0xffffffffu, q1, off);
        q2 += __shfl_down_sync(0xffffffffu, q2, off);
        q3 += __shfl_down_sync(0xffffffffu, q3, off);
    }
    if ((threadIdx.x & 31) == 0) {
        atomicAdd(&d_stats[0], s0); atomicAdd(&d_stats[1], s1);
        atomicAdd(&d_stats[2], s2); atomicAdd(&d_stats[3], s3);
        atomicAdd(&d_stats[4], q0); atomicAdd(&d_stats[5], q1);
        atomicAdd(&d_stats[6], q2); atomicAdd(&d_stats[7], q3);
    }
}

__global__ void k_stats_r(const float* __restrict__ rx, int rows) {
    const float4* v4 = (const float4*)rx;   // row stride = 8 floats = 2 float4
    float s0 = 0, s1 = 0, s2 = 0, q0 = 0, q1 = 0, q2 = 0;
    for (int r = blockIdx.x * blockDim.x + threadIdx.x; r < rows; r += gridDim.x * blockDim.x) {
        float4 v = v4[r * 2];
        s0 += v.x; q0 += v.x * v.x;
        s1 += v.y; q1 += v.y * v.y;
        s2 += v.z; q2 += v.z * v.z;
    }
    #pragma unroll
    for (int off = 16; off > 0; off >>= 1) {
        s0 += __shfl_down_sync(0xffffffffu, s0, off);
        s1 += __shfl_down_sync(0xffffffffu, s1, off);
        s2 += __shfl_down_sync(0xffffffffu, s2, off);
        q0 += __shfl_down_sync(0xffffffffu, q0, off);
        q1 += __shfl_down_sync(0xffffffffu, q1, off);
        q2 += __shfl_down_sync(0xffffffffu, q2, off);
    }
    if ((threadIdx.x & 31) == 0) {
        atomicAdd(&d_stats[8],  s0); atomicAdd(&d_stats[9],  s1);
        atomicAdd(&d_stats[10], s2); atomicAdd(&d_stats[11], q0);
        atomicAdd(&d_stats[12], q1); atomicAdd(&d_stats[13], q2);
    }
}

__global__ void k_prep(const float* __restrict__ bsw, const float* __restrict__ bsb,
                       const float* __restrict__ brw, const float* __restrict__ brb,
                       int ns, int nr) {
    int t = threadIdx.x;
    if (t < 4) {
        float m = d_stats[t] / (float)ns;
        float var = d_stats[4 + t] / (float)ns - m * m;
        float sc = rsqrtf(var + 1e-5f) * bsw[t];
        d_pre[t] = sc;
        d_pre[4 + t] = bsb[t] - m * sc;
    } else if (t < 7) {
        int c = t - 4;
        float m = d_stats[8 + c] / (float)nr;
        float var = d_stats[11 + c] / (float)nr - m * m;
        float sc = rsqrtf(var + 1e-5f) * brw[c];
        d_pre[8 + c] = sc;
        d_pre[11 + c] = brb[c] - m * sc;
    }
}

// ---------------- feature encoder: X = leaky(bn(x) @ W) ----------------
__global__ void k_feat(const float* __restrict__ sx, const float* __restrict__ rx,
                       const float* __restrict__ wsl, const float* __restrict__ wrl) {
    int node = blockIdx.x;
    int h = threadIdx.x;
    int b = node / (S_ + R_);
    int pos = node - b * (S_ + R_);
    float acc = 0.f;
    if (pos < S_) {
        int i = b * S_ + pos;
        #pragma unroll
        for (int c = 0; c < SC_; c++) {
            float xn = __ldg(sx + i * SC_ + c) * d_pre[c] + d_pre[4 + c];
            acc += xn * __ldg(wsl + c * HC_ + h);
        }
    } else {
        int ri = b * R_ + (pos - S_);
        #pragma unroll
        for (int c = 0; c < RC_; c++) {
            float xn = __ldg(rx + ri * (RC_ + 5) + c) * d_pre[8 + c] + d_pre[11 + c];
            acc += xn * __ldg(wrl + c * HC_ + h);
        }
    }
    d_X[node * HC_ + h] = leaky(acc);
}

// ---------------- o-branch: o = leaky(o_x @ w1 + b1) @ w2 + b2 ----------------
__global__ void k_o(const float* __restrict__ rx,
                    const float* __restrict__ w1, const float* __restrict__ b1,
                    const float* __restrict__ w2, const float* __restrict__ b2) {
    __shared__ float sh[HC_];
    int b = blockIdx.x, h = threadIdx.x;
    float acc = b1[h];
    #pragma unroll
    for (int c = 0; c < 5; c++)
        acc += __ldg(rx + (size_t)(b * R_) * (RC_ + 5) + RC_ + c) * __ldg(w1 + c * HC_ + h);
    sh[h] = leaky(acc);
    __syncthreads();
    if (h < NO_) {
        float o = b2[h];
        #pragma unroll 8
        for (int k = 0; k < HC_; k++) o += sh[k] * __ldg(w2 + k * NO_ + h);
        d_O[b * NO_ + h] = o;
    }
}

// ---------------- GEMM: XW = X @ W (N x 128 @ 128 x 128) ----------------
__global__ void __launch_bounds__(256) k_gemm(const float* __restrict__ W, int n) {
    __shared__ float Ws[64 * 128];  // 32 KB
    __shared__ float Xs[64 * 64];   // 16 KB
    int tid = threadIdx.x, lane = tid & 31, rg = tid >> 5;
    int row0 = blockIdx.x * 64;
    float acc[8][4];
    #pragma unroll
    for (int r = 0; r < 8; r++)
        #pragma unroll
        for (int c = 0; c < 4; c++) acc[r][c] = 0.f;

    const float4* W4 = (const float4*)W;
    const float4* X4 = (const float4*)d_X;
    float4* Ws4 = (float4*)Ws;
    float4* Xs4 = (float4*)Xs;

    for (int kc = 0; kc < 128; kc += 64) {
        #pragma unroll
        for (int i = tid; i < 2048; i += 256) {   // Ws[k][h]
            int k = i >> 5, h4 = i & 31;
            Ws4[i] = W4[(kc + k) * 32 + h4];
        }
        #pragma unroll
        for (int i = tid; i < 1024; i += 256) {   // Xs[r][k]
            int r = i >> 4, k4 = i & 15;
            int row = row0 + r;
            Xs4[i] = (row < n) ? X4[row * 32 + (kc >> 2) + k4]
                               : make_float4(0.f, 0.f, 0.f, 0.f);
        }
        __syncthreads();
        #pragma unroll 4
        for (int k = 0; k < 64; k++) {
            float4 w = Ws4[k * 32 + lane];
            #pragma unroll
            for (int r = 0; r < 8; r++) {
                float xv = Xs[(rg * 8 + r) * 64 + k];
                acc[r][0] += xv * w.x;
                acc[r][1] += xv * w.y;
                acc[r][2] += xv * w.z;
                acc[r][3] += xv * w.w;
            }
        }
        __syncthreads();
    }
    float4* O4 = (float4*)d_XW;
    #pragma unroll
    for (int r = 0; r < 8; r++) {
        int row = row0 + rg * 8 + r;
        if (row < n)
            O4[row * 32 + lane] = make_float4(acc[r][0], acc[r][1], acc[r][2], acc[r][3]);
    }
}

// ---------------- fused gather + self-loop + bias + leaky + residual ----------------
__global__ void k_gather(const float* __restrict__ bias, int n) {
    int warp = (blockIdx.x * blockDim.x + threadIdx.x) >> 5;
    int lane = threadIdx.x & 31;
    if (warp >= n) return;
    int cnt = d_degi[warp];
    int start = d_offs[warp];
    float di = d_dinv[warp];
    const float4* xw4 = (const float4*)d_XW;

    float4 sv = xw4[warp * 32 + lane];  // self loop
    float ns = di * di;
    float4 acc = make_float4(sv.x * ns, sv.y * ns, sv.z * ns, sv.w * ns);

    for (int j = 0; j < cnt; j++) {
        int s = __ldg(d_esrc + start + j);
        float nw = __ldg(d_enorm + start + j);
        float4 v = __ldg(xw4 + (size_t)s * 32 + lane);
        acc.x += nw * v.x;
        acc.y += nw * v.y;
        acc.z += nw * v.z;
        acc.w += nw * v.w;
    }
    float4 bv = ((const float4*)bias)[lane];
    acc.x = leaky(acc.x + bv.x);
    acc.y = leaky(acc.y + bv.y);
    acc.z = leaky(acc.z + bv.z);
    acc.w = leaky(acc.w + bv.w);
    float4* X4 = (float4*)d_X;
    float4 xv = X4[warp * 32 + lane];
    X4[warp * 32 + lane] = make_float4(xv.x + acc.x, xv.y + acc.y, xv.z + acc.z, xv.w + acc.w);
}

// ---------------- mean-pool over HC ----------------
__global__ void k_pool(int n) {
    int warp = (blockIdx.x * blockDim.x + threadIdx.x) >> 5;
    int lane = threadIdx.x & 31;
    if (warp >= n) return;
    const float4* X4 = (const float4*)d_X;
    float4 v = X4[warp * 32 + lane];
    float s = v.x + v.y + v.z + v.w;
    #pragma unroll
    for (int off = 16; off > 0; off >>= 1) s += __shfl_down_sync(0xffffffffu, s, off);
    if (lane == 0) d_pooled[warp] = s * (1.f / (float)HC_);
}

// ---------------- readout: z = exp(pooled@Wr+br)/(sum+1) * exp(o) ----------------
__global__ void k_final(const float* __restrict__ lw, const float* __restrict__ lb,
                        float* __restrict__ out) {
    __shared__ float sh[128 * NO_];
    int b = blockIdx.x, t = threadIdx.x;
    float acc[NO_];
    #pragma unroll
    for (int j = 0; j < NO_; j++) acc[j] = 0.f;
    for (int tt = t; tt < S_ + R_; tt += 128) {
        float p = d_pooled[b * (S_ + R_) + tt];
        #pragma unroll
        for (int j = 0; j < NO_; j++) acc[j] += p * __ldg(lw + tt * NO_ + j);
    }
    #pragma unroll
    for (int j = 0; j < NO_; j++) sh[t * NO_ + j] = acc[j];
    __syncthreads();
    for (int off = 64; off > 0; off >>= 1) {
        if (t < off) {
            #pragma unroll
            for (int j = 0; j < NO_; j++) sh[t * NO_ + j] += sh[(t + off) * NO_ + j];
        }
        __syncthreads();
    }
    if (t == 0) {
        float z[NO_], sum = 0.f;
        #pragma unroll
        for (int j = 0; j < NO_; j++) { z[j] = expf(sh[j] + lb[j]); sum += z[j]; }
        float inv = 1.f / (sum + 1.f);
        #pragma unroll
        for (int j = 0; j < NO_; j++)
            out[b * NO_ + j] = z[j] * inv * expf(d_O[b * NO_ + j]);
    }
}

// ---------------- host orchestration ----------------
extern "C" void kernel_launch(void* const* d_in, const int* in_sizes, int n_in,
                              void* d_out, int out_size) {
    const float* s_x     = (const float*)d_in[0];
    const float* r_x     = (const float*)d_in[1];
    const int*   ei      = (const int*)d_in[2];
    const float* bn_s_w  = (const float*)d_in[3];
    const float* bn_s_b  = (const float*)d_in[4];
    const float* bn_r_w  = (const float*)d_in[5];
    const float* bn_r_b  = (const float*)d_in[6];
    const float* lin_s_w = (const float*)d_in[7];
    const float* lin_r_w = (const float*)d_in[8];
    const float* conv_w  = (const float*)d_in[9];
    const float* conv_b  = (const float*)d_in[10];
    const float* linr_w  = (const float*)d_in[11];
    const float* linr_b  = (const float*)d_in[12];
    const float* lino_w1 = (const float*)d_in[13];
    const float* lino_b1 = (const float*)d_in[14];
    const float* lino_w2 = (const float*)d_in[15];
    const float* lino_b2 = (const float*)d_in[16];
    float* out = (float*)d_out;

    int E  = in_sizes[2] / 2;
    int Bn = in_sizes[1] / (R_ * (RC_ + 5));
    int n  = Bn * (S_ + R_);
    int rowsS = Bn * S_, rowsR = Bn * R_;
    const int* src = ei;
    const int* dst = ei + E;

    // degree + CSR build (amortized over 4 layers; atomic-free aggregation after)
    k_zero<<<(n + 255) / 256, 256>>>(n);
    k_count<<<(E + 255) / 256, 256>>>(dst, E);
    k_dinv<<<(n + 255) / 256, 256>>>(n);
    int nb1 = (n + 511) / 512;
    k_scan1<<<nb1, 512>>>(n);
    k_scan2<<<1, 512>>>(nb1);
    k_scan3<<<(n + 255) / 256, 256>>>(n);
    k_fill<<<(E + 255) / 256, 256>>>(src, dst, E);

    // batchnorm + encoders
    k_stats_s<<<96, 256>>>(s_x, rowsS);
    k_stats_r<<<192, 256>>>(r_x, rowsR);
    k_prep<<<1, 32>>>(bn_s_w, bn_s_b, bn_r_w, bn_r_b, rowsS, rowsR);
    k_feat<<<n, 128>>>(s_x, r_x, lin_s_w, lin_r_w);
    k_o<<<Bn, 128>>>(r_x, lino_w1, lino_b1, lino_w2, lino_b2);

    // 4 GCN layers
    int gemm_blocks = (n + 63) / 64;
    int gather_blocks = (n * 32 + 255) / 256;
    for (int l = 0; l < L_; l++) {
        k_gemm<<<gemm_blocks, 256>>>(conv_w + (size_t)l * HC_ * HC_, n);
        k_gather<<<gather_blocks, 256>>>(conv_b + l * HC_, n);
    }

    // readout
    k_pool<<<(n * 32 + 255) / 256, 256>>>(n);
    k_final<<<Bn, 128>>>(linr_w, linr_b, out);
}